// round 15
// baseline (speedup 1.0000x reference)
#include <cuda_runtime.h>

#define BB 4
#define HHH 64
#define LL 4096
#define EE 192
#define NNS 16
#define RR 6
#define KK 4
#define DM 96
#define BL (BB*LL)
#define C152 152
#define NCH 64
#define CHL 64    // LL/NCH

typedef unsigned long long u64;

// ------------------------- device scratch (no allocations) ------------------
__device__ float g_xx[BL*EE];
__device__ float g_z [BL*EE];
__device__ float g_xc[BL*EE];
__device__ float g_P [BL*C152];
__device__ float2 g_dU2[16*LL*EE];     // {delta, delta*u} in (bk, l, e)
__device__ float g_B4[16*LL*16];       // (bk, l, n) natural state order
__device__ float g_C4[16*LL*16];
__device__ float g_y [16*LL*EE];       // (bk, l, e)
__device__ float g_ym[BL*EE];
// chunked-scan carries: chain = bk*EE+e in [0,3072); natural state order n
__device__ float g_hfin[3072*NCH*16];
__device__ float g_hin [3072*NCH*16];
__device__ float g_Sdd [3072*NCH];

__device__ __forceinline__ float ex2f(float x){
    float y; asm("ex2.approx.f32 %0, %1;" : "=f"(y) : "f"(x)); return y;
}
__device__ __forceinline__ float siluf(float x){
    return x / (1.f + __expf(-x));
}
__device__ __forceinline__ float softplusf(float x){
    return fmaxf(x, 0.f) + __logf(1.f + __expf(-fabsf(x)));
}
__device__ __forceinline__ u64 fma2(u64 a, u64 b, u64 c){
    u64 d; asm("fma.rn.f32x2 %0, %1, %2, %3;" : "=l"(d) : "l"(a), "l"(b), "l"(c));
    return d;
}
__device__ __forceinline__ u64 mul2(u64 a, u64 b){
    u64 d; asm("mul.rn.f32x2 %0, %1, %2;" : "=l"(d) : "l"(a), "l"(b));
    return d;
}
__device__ __forceinline__ u64 pack2(float x, float y){
    u64 d; asm("mov.b64 %0, {%1, %2};" : "=l"(d) : "f"(x), "f"(y));
    return d;
}
__device__ __forceinline__ void unpack2(u64 v, float& lo, float& hi){
    asm("mov.b64 {%0, %1}, %2;" : "=f"(lo), "=f"(hi) : "l"(v));
}

// ------------------------- tiled GEMM: out[m,n] = sum_k X[m,k]*W[n,k] -------
template<int KD, int MODE>
__global__ void __launch_bounds__(256)
k_gemm(const float* __restrict__ Xp, const float* __restrict__ W,
       float* __restrict__ Out, int Nn)
{
    __shared__ float Xs[32][132];
    __shared__ float Ws[32][68];
    const float* __restrict__ X = (MODE==0) ? (const float*)g_xc
                                : (MODE==2) ? (const float*)g_ym : Xp;
    const int m0 = blockIdx.x * 128;
    const int n0 = blockIdx.y * 64;
    const int t  = threadIdx.x;
    const int ty = t >> 4, tx = t & 15;
    u64 acc2[4][4];
    #pragma unroll
    for (int i=0;i<4;i++)
        #pragma unroll
        for (int j=0;j<4;j++) acc2[i][j] = 0ull;

    const int lc4 = (t & 7) * 4;
    const int lr0 = t >> 3;
    const int NKC = KD/32;

    float4 xv[4], wv2[2];
    #pragma unroll
    for (int i = 0; i < 4; i++)
        xv[i] = *(const float4*)&X[(m0 + lr0 + 32*i)*KD + lc4];
    #pragma unroll
    for (int i = 0; i < 2; i++){
        int nr = n0 + lr0 + 32*i;
        wv2[i] = (nr < Nn) ? *(const float4*)&W[nr*KD + lc4]
                           : make_float4(0.f,0.f,0.f,0.f);
    }

    #pragma unroll
    for (int kc = 0; kc < NKC; kc++){
        #pragma unroll
        for (int i = 0; i < 4; i++){
            int r = lr0 + 32*i;
            Xs[lc4+0][r] = xv[i].x; Xs[lc4+1][r] = xv[i].y;
            Xs[lc4+2][r] = xv[i].z; Xs[lc4+3][r] = xv[i].w;
        }
        #pragma unroll
        for (int i = 0; i < 2; i++){
            int r = lr0 + 32*i;
            Ws[lc4+0][r] = wv2[i].x; Ws[lc4+1][r] = wv2[i].y;
            Ws[lc4+2][r] = wv2[i].z; Ws[lc4+3][r] = wv2[i].w;
        }
        __syncthreads();

        if (kc + 1 < NKC){
            #pragma unroll
            for (int i = 0; i < 4; i++)
                xv[i] = *(const float4*)&X[(m0 + lr0 + 32*i)*KD + (kc+1)*32 + lc4];
            #pragma unroll
            for (int i = 0; i < 2; i++){
                int nr = n0 + lr0 + 32*i;
                wv2[i] = (nr < Nn) ? *(const float4*)&W[nr*KD + (kc+1)*32 + lc4]
                                   : make_float4(0.f,0.f,0.f,0.f);
            }
        }

        #pragma unroll
        for (int k = 0; k < 32; k++){
            const u64* xp = (const u64*)&Xs[k][ty*8];
            u64 x2[4] = {xp[0], xp[1], xp[2], xp[3]};
            float4 wv = *(const float4*)&Ws[k][tx*4];
            u64 w2[4] = {pack2(wv.x,wv.x), pack2(wv.y,wv.y),
                         pack2(wv.z,wv.z), pack2(wv.w,wv.w)};
            #pragma unroll
            for (int i=0;i<4;i++)
                #pragma unroll
                for (int j=0;j<4;j++) acc2[i][j] = fma2(x2[i], w2[j], acc2[i][j]);
        }
        __syncthreads();
    }
    #pragma unroll
    for (int i=0;i<4;i++){
        #pragma unroll
        for (int j=0;j<4;j++){
            float lo, hi;
            unpack2(acc2[i][j], lo, hi);
            int n = n0 + tx*4 + j;
            int mA = m0 + ty*8 + 2*i;
            #pragma unroll
            for (int pp = 0; pp < 2; pp++){
                int m = mA + pp;
                float v = pp ? hi : lo;
                if (MODE == 1){
                    if (n < EE) g_xx[m*EE + n] = v;
                    else        g_z [m*EE + n - EE] = siluf(v);
                } else if (MODE == 0){
                    if (n < Nn) g_P[m*C152 + n] = v;
                } else {
                    if (n < Nn) Out[m*Nn + n] = v;
                }
            }
        }
    }
}

// ------------------------- depthwise 3x3 conv + bias + silu -----------------
__global__ void __launch_bounds__(256) k_conv(const float* __restrict__ cw, const float* __restrict__ cb)
{
    __shared__ float xs_s[3][64][48];
    __shared__ float cw_s[48][9];
    const int e0 = blockIdx.x * 48;
    const int h  = blockIdx.y;
    const int b  = blockIdx.z;
    const int t  = threadIdx.x;

    for (int idx = t; idx < 3*64*48; idx += 256){
        int row = idx / (64*48);
        int rem = idx - row*(64*48);
        int w  = rem / 48;
        int ec = rem - w*48;
        int hh = h + row - 1;
        float v = 0.f;
        if (hh >= 0 && hh < HHH)
            v = g_xx[(b*LL + hh*64 + w)*EE + e0 + ec];
        xs_s[row][w][ec] = v;
    }
    for (int idx = t; idx < 48*9; idx += 256){
        int ec = idx / 9, q = idx - ec*9;
        cw_s[ec][q] = cw[(e0+ec)*9 + q];
    }
    __syncthreads();

    for (int o = t; o < 64*48; o += 256){
        int w  = o / 48;
        int ec = o - w*48;
        float acc = cb[e0+ec];
        #pragma unroll
        for (int dh = 0; dh < 3; dh++){
            #pragma unroll
            for (int dw = 0; dw < 3; dw++){
                int ww = w + dw - 1;
                if (ww >= 0 && ww < 64)
                    acc = fmaf(xs_s[dh][ww][ec], cw_s[ec][dh*3+dw], acc);
            }
        }
        g_xc[(b*LL + h*64 + w)*EE + e0 + ec] = siluf(acc);
    }
}

// ------------------------- prep: fused k / k+2 (shared xc gather) -----------
// direction k at position l and direction k+2 at position LL-1-l read the SAME
// canonical row, so one block computes both. grid = B*2*128.
__global__ void __launch_bounds__(256) k_prep(const float* __restrict__ dtw, const float* __restrict__ dtb)
{
    __shared__ float Pt [32][39];
    __shared__ float Pt2[32][39];
    __shared__ float xr[32][193];
    __shared__ float dtws[2*EE*RR];
    __shared__ float dtbs[2*EE];
    __shared__ int   clm[32];
    const int bid = blockIdx.x;
    const int lt = bid & 127;
    const int k  = (bid >> 7) & 1;
    const int b  = bid >> 8;
    const int k2 = k + 2;
    const int l0 = lt * 32;
    const int t  = threadIdx.x;

    if (t < 32){
        int l = l0 + t, cl;
        if (k == 0) cl = l;
        else        cl = (l & 63)*64 + (l >> 6);
        clm[t] = cl;
    }
    for (int idx = t; idx < EE*RR; idx += 256){
        dtws[idx]         = dtw[k *EE*RR + idx];
        dtws[EE*RR + idx] = dtw[k2*EE*RR + idx];
    }
    for (int idx = t; idx < EE; idx += 256){
        dtbs[idx]      = dtb[k *EE + idx];
        dtbs[EE + idx] = dtb[k2*EE + idx];
    }
    __syncthreads();
    for (int idx = t; idx < 32*38; idx += 256){
        int r = idx / 38, c = idx - r*38;
        long row = (long)(b*LL + clm[r])*C152;
        Pt [r][c] = g_P[row + k *38 + c];
        Pt2[r][c] = g_P[row + k2*38 + c];
    }
    for (int idx = t; idx < 32*48; idx += 256){
        int r = idx / 48, c = idx - r*48;
        float4 v = *(const float4*)&g_xc[(b*LL + clm[r])*EE + c*4];
        xr[r][c*4+0] = v.x; xr[r][c*4+1] = v.y;
        xr[r][c*4+2] = v.z; xr[r][c*4+3] = v.w;
    }
    __syncthreads();

    const int bk  = b*KK + k;
    const int bk2 = b*KK + k2;
    if (t < EE){
        const int e = t;
        float wreg[RR], wreg2[RR];
        #pragma unroll
        for (int r = 0; r < RR; r++){
            wreg [r] = dtws[e*RR + r];
            wreg2[r] = dtws[EE*RR + e*RR + r];
        }
        const float db  = dtbs[e];
        const float db2 = dtbs[EE + e];
        #pragma unroll 4
        for (int l = 0; l < 32; l++){
            float acc = db, acc2 = db2;
            #pragma unroll
            for (int r = 0; r < RR; r++){
                acc  = fmaf(Pt [l][r], wreg [r], acc);
                acc2 = fmaf(Pt2[l][r], wreg2[r], acc2);
            }
            float dl  = softplusf(acc);
            float dl2 = softplusf(acc2);
            float u   = xr[l][e];
            g_dU2[((long)bk *LL + l0 + l)*EE + e]        = make_float2(dl,  dl*u);
            g_dU2[((long)bk2*LL + (LL-1-l0-l))*EE + e]   = make_float2(dl2, dl2*u);
        }
    }
    for (int idx = t; idx < 32*16; idx += 256){
        int pos = idx >> 4, n = idx & 15;
        long o  = ((long)bk *LL + l0 + pos)*16 + n;
        long o2 = ((long)bk2*LL + (LL-1-l0-pos))*16 + n;
        g_B4[o]  = Pt [pos][6  + n];
        g_C4[o]  = Pt [pos][22 + n];
        g_B4[o2] = Pt2[pos][6  + n];
        g_C4[o2] = Pt2[pos][22 + n];
    }
}

// ------------------------- scan pass 1: lane = full chain (16 states) -------
// block = (bk, chunk): 6 warps x 32 lanes = 192 e-chains; B staged to smem.
// chunks 0..62. grid 16*63 = 1008 blocks.
__global__ void __launch_bounds__(192) k_scan1(const float* __restrict__ A_logs)
{
    __shared__ float Bs[CHL*16];       // 4KB

    const int t    = threadIdx.x;
    const int lane = t & 31;
    const int w    = t >> 5;
    const int bk    = blockIdx.x / 63;
    const int chunk = blockIdx.x - bk*63;
    const int e  = w*32 + lane;
    const int k  = bk & 3;
    const int l0 = chunk*CHL;

    {
        const float4* src = (const float4*)(g_B4 + ((long)bk*LL + l0)*16);
        float4* dst = (float4*)Bs;
        for (int i = t; i < CHL*4; i += 192) dst[i] = src[i];
    }

    const float L2E = 1.4426950408889634f;
    const int abase = (k*EE + e)*NNS;
    bool okl = true;
    #pragma unroll
    for (int n = 0; n < 16; n++){
        float av = -__expf(A_logs[abase + n]);
        okl &= fabsf(av + (float)(n+1)) < 1e-4f*(float)(n+1);
    }
    const bool ok = __all_sync(0xffffffffu, okl);

    const int ch = bk*EE + e;
    const float2* __restrict__ pdu = g_dU2 + ((long)bk*LL + l0)*EE + e;

    __syncthreads();

    u64 h2[8];
    #pragma unroll
    for (int j = 0; j < 8; j++) h2[j] = 0ull;
    float sdd = 0.f;

    if (ok){
        #pragma unroll 4
        for (int l = 0; l < CHL; l++){
            float2 du = pdu[(long)l*EE];
            float tt = ex2f(-L2E*du.x);
            float t2 = tt*tt, t4v = t2*t2;
            u64 s2 = pack2(t2,t2), s4 = pack2(t4v,t4v);
            u64 d0 = pack2(tt, t2);
            u64 d1 = mul2(d0, s2);
            u64 d2 = mul2(d0, s4);
            u64 d3 = mul2(d1, s4);
            u64 d4 = mul2(d2, s4);
            u64 d5 = mul2(d3, s4);
            u64 d6 = mul2(d4, s4);
            u64 d7 = mul2(d5, s4);
            u64 us2 = pack2(du.y, du.y);
            const u64* bp = (const u64*)(Bs + l*16);
            h2[0] = fma2(d0, h2[0], mul2(us2, bp[0]));
            h2[1] = fma2(d1, h2[1], mul2(us2, bp[1]));
            h2[2] = fma2(d2, h2[2], mul2(us2, bp[2]));
            h2[3] = fma2(d3, h2[3], mul2(us2, bp[3]));
            h2[4] = fma2(d4, h2[4], mul2(us2, bp[4]));
            h2[5] = fma2(d5, h2[5], mul2(us2, bp[5]));
            h2[6] = fma2(d6, h2[6], mul2(us2, bp[6]));
            h2[7] = fma2(d7, h2[7], mul2(us2, bp[7]));
            sdd += du.x;
        }
    } else {
        #pragma unroll 1
        for (int l = 0; l < CHL; l++){
            float2 du = pdu[(long)l*EE];
            u64 us2 = pack2(du.y, du.y);
            const u64* bp = (const u64*)(Bs + l*16);
            #pragma unroll
            for (int j = 0; j < 8; j++){
                float alo = -L2E*__expf(A_logs[abase + 2*j]);
                float ahi = -L2E*__expf(A_logs[abase + 2*j+1]);
                u64 dA = pack2(ex2f(du.x*alo), ex2f(du.x*ahi));
                h2[j] = fma2(dA, h2[j], mul2(us2, bp[j]));
            }
            sdd += du.x;
        }
    }
    u64* hfo = (u64*)&g_hfin[((long)ch*NCH + chunk)*16];
    #pragma unroll
    for (int j = 0; j < 8; j++) hfo[j] = h2[j];
    g_Sdd[ch*NCH + chunk] = sdd;
}

// ------------------------- scan mid: carry propagation ----------------------
__global__ void __launch_bounds__(256) k_scanmid(const float* __restrict__ A_logs)
{
    const int tid = blockIdx.x*256 + threadIdx.x;   // [0, 49152)
    const int ch = tid >> 4;
    const int n  = tid & 15;
    const int e  = ch % EE;
    const int k  = (ch / EE) & 3;
    float a = -__expf(A_logs[(k*EE + e)*NNS + n]);

    float h = 0.f;
    #pragma unroll
    for (int c = 0; c < NCH; c++){
        g_hin[((long)ch*NCH + c)*16 + n] = h;
        if (c < NCH-1){
            float hf = g_hfin[((long)ch*NCH + c)*16 + n];
            float S = g_Sdd[ch*NCH + c];
            h = hf + __expf(a*S)*h;
        }
    }
}

// ------------------------- scan pass 2: lane = full chain, with y -----------
// block = (bk, chunk): 192 threads; B,C staged. all 64 chunks: grid 1024.
__global__ void __launch_bounds__(192) k_scan2(const float* __restrict__ A_logs)
{
    __shared__ float Bs[CHL*16];       // 4KB
    __shared__ float Cs[CHL*16];       // 4KB

    const int t    = threadIdx.x;
    const int lane = t & 31;
    const int w    = t >> 5;
    const int bk    = blockIdx.x >> 6;
    const int chunk = blockIdx.x & 63;
    const int e  = w*32 + lane;
    const int k  = bk & 3;
    const int l0 = chunk*CHL;

    {
        const float4* srcB = (const float4*)(g_B4 + ((long)bk*LL + l0)*16);
        const float4* srcC = (const float4*)(g_C4 + ((long)bk*LL + l0)*16);
        float4* dstB = (float4*)Bs;
        float4* dstC = (float4*)Cs;
        for (int i = t; i < CHL*4; i += 192){
            dstB[i] = srcB[i];
            dstC[i] = srcC[i];
        }
    }

    const float L2E = 1.4426950408889634f;
    const int abase = (k*EE + e)*NNS;
    bool okl = true;
    #pragma unroll
    for (int n = 0; n < 16; n++){
        float av = -__expf(A_logs[abase + n]);
        okl &= fabsf(av + (float)(n+1)) < 1e-4f*(float)(n+1);
    }
    const bool ok = __all_sync(0xffffffffu, okl);

    const int ch = bk*EE + e;
    const float2* __restrict__ pdu = g_dU2 + ((long)bk*LL + l0)*EE + e;
    float* __restrict__ py = g_y + ((long)bk*LL + l0)*EE + e;

    u64 h2[8];
    {
        const u64* hp = (const u64*)&g_hin[((long)ch*NCH + chunk)*16];
        #pragma unroll
        for (int j = 0; j < 8; j++) h2[j] = hp[j];
    }

    __syncthreads();

    if (ok){
        #pragma unroll 4
        for (int l = 0; l < CHL; l++){
            float2 du = pdu[(long)l*EE];
            float tt = ex2f(-L2E*du.x);
            float t2 = tt*tt, t4v = t2*t2;
            u64 s2 = pack2(t2,t2), s4 = pack2(t4v,t4v);
            u64 d0 = pack2(tt, t2);
            u64 d1 = mul2(d0, s2);
            u64 d2 = mul2(d0, s4);
            u64 d3 = mul2(d1, s4);
            u64 d4 = mul2(d2, s4);
            u64 d5 = mul2(d3, s4);
            u64 d6 = mul2(d4, s4);
            u64 d7 = mul2(d5, s4);
            u64 us2 = pack2(du.y, du.y);
            const u64* bp = (const u64*)(Bs + l*16);
            const u64* cp = (const u64*)(Cs + l*16);
            h2[0] = fma2(d0, h2[0], mul2(us2, bp[0]));
            h2[1] = fma2(d1, h2[1], mul2(us2, bp[1]));
            h2[2] = fma2(d2, h2[2], mul2(us2, bp[2]));
            h2[3] = fma2(d3, h2[3], mul2(us2, bp[3]));
            h2[4] = fma2(d4, h2[4], mul2(us2, bp[4]));
            h2[5] = fma2(d5, h2[5], mul2(us2, bp[5]));
            h2[6] = fma2(d6, h2[6], mul2(us2, bp[6]));
            h2[7] = fma2(d7, h2[7], mul2(us2, bp[7]));
            u64 acc = mul2(h2[0], cp[0]);
            acc = fma2(h2[1], cp[1], acc);
            acc = fma2(h2[2], cp[2], acc);
            acc = fma2(h2[3], cp[3], acc);
            acc = fma2(h2[4], cp[4], acc);
            acc = fma2(h2[5], cp[5], acc);
            acc = fma2(h2[6], cp[6], acc);
            acc = fma2(h2[7], cp[7], acc);
            float lo, hi; unpack2(acc, lo, hi);
            py[(long)l*EE] = lo + hi;
        }
    } else {
        #pragma unroll 1
        for (int l = 0; l < CHL; l++){
            float2 du = pdu[(long)l*EE];
            u64 us2 = pack2(du.y, du.y);
            const u64* bp = (const u64*)(Bs + l*16);
            const u64* cp = (const u64*)(Cs + l*16);
            u64 acc = 0ull;
            #pragma unroll
            for (int j = 0; j < 8; j++){
                float alo = -L2E*__expf(A_logs[abase + 2*j]);
                float ahi = -L2E*__expf(A_logs[abase + 2*j+1]);
                u64 dA = pack2(ex2f(du.x*alo), ex2f(du.x*ahi));
                h2[j] = fma2(dA, h2[j], mul2(us2, bp[j]));
                acc = fma2(h2[j], cp[j], acc);
            }
            float lo, hi; unpack2(acc, lo, hi);
            py[(long)l*EE] = lo + hi;
        }
    }
}

// ------------------------- merge + D*xc + LayerNorm + gate ------------------
__global__ void __launch_bounds__(256) k_merge(const float* __restrict__ Ds, const float* __restrict__ gamma,
                        const float* __restrict__ beta)
{
    __shared__ float sumD[EE];
    const int l0 = blockIdx.x * 32;
    const int b  = blockIdx.y;
    const int t  = threadIdx.x;
    if (t < EE) sumD[t] = Ds[t] + Ds[EE + t] + Ds[2*EE + t] + Ds[3*EE + t];
    __syncthreads();

    const int li = t >> 3, ts = t & 7;
    const int l  = l0 + li;
    const int lw = (l & 63)*64 + (l >> 6);

    const float* __restrict__ y0p = g_y + ((long)(b*4 + 0)*LL + l)*EE;
    const float* __restrict__ y1p = g_y + ((long)(b*4 + 1)*LL + lw)*EE;
    const float* __restrict__ y2p = g_y + ((long)(b*4 + 2)*LL + (LL-1-l))*EE;
    const float* __restrict__ y3p = g_y + ((long)(b*4 + 3)*LL + (LL-1-lw))*EE;
    const float* __restrict__ xcp = g_xc + (long)(b*LL + l)*EE;
    const float* __restrict__ zp  = g_z  + (long)(b*LL + l)*EE;
    float* __restrict__ ymp = g_ym + (long)(b*LL + l)*EE;

    float v[6][4];
    float s1 = 0.f, s2 = 0.f;
    #pragma unroll
    for (int m = 0; m < 6; m++){
        int e4 = (ts + 8*m)*4;
        float4 a0 = *(const float4*)(y0p + e4);
        float4 a1 = *(const float4*)(y1p + e4);
        float4 a2 = *(const float4*)(y2p + e4);
        float4 a3 = *(const float4*)(y3p + e4);
        float4 xc = *(const float4*)(xcp + e4);
        float4 sd = *(const float4*)(&sumD[e4]);
        v[m][0] = a0.x + a1.x + a2.x + a3.x + sd.x*xc.x;
        v[m][1] = a0.y + a1.y + a2.y + a3.y + sd.y*xc.y;
        v[m][2] = a0.z + a1.z + a2.z + a3.z + sd.z*xc.z;
        v[m][3] = a0.w + a1.w + a2.w + a3.w + sd.w*xc.w;
        #pragma unroll
        for (int q = 0; q < 4; q++){ s1 += v[m][q]; s2 += v[m][q]*v[m][q]; }
    }
    #pragma unroll
    for (int o = 1; o < 8; o <<= 1){
        s1 += __shfl_xor_sync(0xffffffffu, s1, o);
        s2 += __shfl_xor_sync(0xffffffffu, s2, o);
    }
    const float inv = 1.f / (float)EE;
    float mu = s1 * inv;
    float var = s2 * inv - mu*mu;
    float rstd = rsqrtf(var + 1e-5f);

    #pragma unroll
    for (int m = 0; m < 6; m++){
        int e4 = (ts + 8*m)*4;
        float4 gm = *(const float4*)(gamma + e4);
        float4 bt = *(const float4*)(beta + e4);
        float4 zz = *(const float4*)(zp + e4);
        float4 o4;
        o4.x = ((v[m][0]-mu)*rstd*gm.x + bt.x) * zz.x;
        o4.y = ((v[m][1]-mu)*rstd*gm.y + bt.y) * zz.y;
        o4.z = ((v[m][2]-mu)*rstd*gm.z + bt.z) * zz.z;
        o4.w = ((v[m][3]-mu)*rstd*gm.w + bt.w) * zz.w;
        *(float4*)(ymp + e4) = o4;
    }
}

// ------------------------- launcher -----------------------------------------
extern "C" void kernel_launch(void* const* d_in, const int* in_sizes, int n_in,
                              void* d_out, int out_size)
{
    const float* x    = (const float*)d_in[0];
    const float* ipw  = (const float*)d_in[1];
    const float* cw   = (const float*)d_in[2];
    const float* cb   = (const float*)d_in[3];
    const float* xpw  = (const float*)d_in[4];
    const float* dtw  = (const float*)d_in[5];
    const float* dtb  = (const float*)d_in[6];
    const float* alog = (const float*)d_in[7];
    const float* Ds   = (const float*)d_in[8];
    const float* lng  = (const float*)d_in[9];
    const float* lnb  = (const float*)d_in[10];
    const float* opw  = (const float*)d_in[11];
    float* out = (float*)d_out;

    k_gemm<DM, 1><<<dim3(128, 6), 256>>>(x, ipw, nullptr, 2*EE);
    k_conv<<<dim3(4, 64, BB), 256>>>(cw, cb);
    k_gemm<EE, 0><<<dim3(128, 3), 256>>>(nullptr, xpw, nullptr, C152);
    k_prep<<<BB*2*128, 256>>>(dtw, dtb);
    k_scan1<<<16*63, 192>>>(alog);
    k_scanmid<<<192, 256>>>(alog);
    k_scan2<<<16*64, 192>>>(alog);
    k_merge<<<dim3(128, BB), 256>>>(Ds, lng, lnb);
    k_gemm<EE, 2><<<dim3(128, 2), 256>>>(nullptr, opw, out, DM);
}

// round 16
// speedup vs baseline: 1.0495x; 1.0495x over previous
#include <cuda_runtime.h>

#define BB 4
#define HHH 64
#define LL 4096
#define EE 192
#define NNS 16
#define RR 6
#define KK 4
#define DM 96
#define BL (BB*LL)
#define C152 152
#define NCH 32
#define CHL 128   // LL/NCH

typedef unsigned long long u64;

// ------------------------- device scratch (no allocations) ------------------
__device__ float g_xx[BL*EE];
__device__ float g_z [BL*EE];
__device__ float g_xc[BL*EE];
__device__ float g_P [BL*C152];
__device__ float2 g_dU2[16*LL*EE];     // {delta, delta*u} in (bk, l, e)
__device__ float g_B4[16*LL*16];       // (bk, l, n) natural state order
__device__ float g_C4[16*LL*16];
__device__ float g_y [16*LL*EE];       // (bk, l, e)
__device__ float g_ym[BL*EE];
// chunked-scan carries: chain = bk*EE+e in [0,3072); natural state order n
__device__ float g_hfin[3072*NCH*16];
__device__ float g_hin [3072*NCH*16];
__device__ float g_Sdd [3072*NCH];

__device__ __forceinline__ float ex2f(float x){
    float y; asm("ex2.approx.f32 %0, %1;" : "=f"(y) : "f"(x)); return y;
}
__device__ __forceinline__ float siluf(float x){
    return x / (1.f + __expf(-x));
}
__device__ __forceinline__ float softplusf(float x){
    return fmaxf(x, 0.f) + __logf(1.f + __expf(-fabsf(x)));
}
__device__ __forceinline__ u64 fma2(u64 a, u64 b, u64 c){
    u64 d; asm("fma.rn.f32x2 %0, %1, %2, %3;" : "=l"(d) : "l"(a), "l"(b), "l"(c));
    return d;
}
__device__ __forceinline__ u64 mul2(u64 a, u64 b){
    u64 d; asm("mul.rn.f32x2 %0, %1, %2;" : "=l"(d) : "l"(a), "l"(b));
    return d;
}
__device__ __forceinline__ u64 pack2(float x, float y){
    u64 d; asm("mov.b64 %0, {%1, %2};" : "=l"(d) : "f"(x), "f"(y));
    return d;
}
__device__ __forceinline__ void unpack2(u64 v, float& lo, float& hi){
    asm("mov.b64 {%0, %1}, %2;" : "=f"(lo), "=f"(hi) : "l"(v));
}

// ------------------------- tiled GEMM: out[m,n] = sum_k X[m,k]*W[n,k] -------
template<int KD, int MODE>
__global__ void __launch_bounds__(256)
k_gemm(const float* __restrict__ Xp, const float* __restrict__ W,
       float* __restrict__ Out, int Nn)
{
    __shared__ float Xs[32][132];
    __shared__ float Ws[32][68];
    const float* __restrict__ X = (MODE==0) ? (const float*)g_xc
                                : (MODE==2) ? (const float*)g_ym : Xp;
    const int m0 = blockIdx.x * 128;
    const int n0 = blockIdx.y * 64;
    const int t  = threadIdx.x;
    const int ty = t >> 4, tx = t & 15;
    u64 acc2[4][4];
    #pragma unroll
    for (int i=0;i<4;i++)
        #pragma unroll
        for (int j=0;j<4;j++) acc2[i][j] = 0ull;

    const int lc4 = (t & 7) * 4;
    const int lr0 = t >> 3;
    const int NKC = KD/32;

    float4 xv[4], wv2[2];
    #pragma unroll
    for (int i = 0; i < 4; i++)
        xv[i] = *(const float4*)&X[(m0 + lr0 + 32*i)*KD + lc4];
    #pragma unroll
    for (int i = 0; i < 2; i++){
        int nr = n0 + lr0 + 32*i;
        wv2[i] = (nr < Nn) ? *(const float4*)&W[nr*KD + lc4]
                           : make_float4(0.f,0.f,0.f,0.f);
    }

    #pragma unroll
    for (int kc = 0; kc < NKC; kc++){
        #pragma unroll
        for (int i = 0; i < 4; i++){
            int r = lr0 + 32*i;
            Xs[lc4+0][r] = xv[i].x; Xs[lc4+1][r] = xv[i].y;
            Xs[lc4+2][r] = xv[i].z; Xs[lc4+3][r] = xv[i].w;
        }
        #pragma unroll
        for (int i = 0; i < 2; i++){
            int r = lr0 + 32*i;
            Ws[lc4+0][r] = wv2[i].x; Ws[lc4+1][r] = wv2[i].y;
            Ws[lc4+2][r] = wv2[i].z; Ws[lc4+3][r] = wv2[i].w;
        }
        __syncthreads();

        if (kc + 1 < NKC){
            #pragma unroll
            for (int i = 0; i < 4; i++)
                xv[i] = *(const float4*)&X[(m0 + lr0 + 32*i)*KD + (kc+1)*32 + lc4];
            #pragma unroll
            for (int i = 0; i < 2; i++){
                int nr = n0 + lr0 + 32*i;
                wv2[i] = (nr < Nn) ? *(const float4*)&W[nr*KD + (kc+1)*32 + lc4]
                                   : make_float4(0.f,0.f,0.f,0.f);
            }
        }

        #pragma unroll
        for (int k = 0; k < 32; k++){
            const u64* xp = (const u64*)&Xs[k][ty*8];
            u64 x2[4] = {xp[0], xp[1], xp[2], xp[3]};
            float4 wv = *(const float4*)&Ws[k][tx*4];
            u64 w2[4] = {pack2(wv.x,wv.x), pack2(wv.y,wv.y),
                         pack2(wv.z,wv.z), pack2(wv.w,wv.w)};
            #pragma unroll
            for (int i=0;i<4;i++)
                #pragma unroll
                for (int j=0;j<4;j++) acc2[i][j] = fma2(x2[i], w2[j], acc2[i][j]);
        }
        __syncthreads();
    }
    #pragma unroll
    for (int i=0;i<4;i++){
        #pragma unroll
        for (int j=0;j<4;j++){
            float lo, hi;
            unpack2(acc2[i][j], lo, hi);
            int n = n0 + tx*4 + j;
            int mA = m0 + ty*8 + 2*i;
            #pragma unroll
            for (int pp = 0; pp < 2; pp++){
                int m = mA + pp;
                float v = pp ? hi : lo;
                if (MODE == 1){
                    if (n < EE) g_xx[m*EE + n] = v;
                    else        g_z [m*EE + n - EE] = siluf(v);
                } else if (MODE == 0){
                    if (n < Nn) g_P[m*C152 + n] = v;
                } else {
                    if (n < Nn) Out[m*Nn + n] = v;
                }
            }
        }
    }
}

// ------------------------- depthwise 3x3 conv + bias + silu -----------------
__global__ void __launch_bounds__(256) k_conv(const float* __restrict__ cw, const float* __restrict__ cb)
{
    __shared__ float xs_s[3][64][48];
    __shared__ float cw_s[48][9];
    const int e0 = blockIdx.x * 48;
    const int h  = blockIdx.y;
    const int b  = blockIdx.z;
    const int t  = threadIdx.x;

    for (int idx = t; idx < 3*64*48; idx += 256){
        int row = idx / (64*48);
        int rem = idx - row*(64*48);
        int w  = rem / 48;
        int ec = rem - w*48;
        int hh = h + row - 1;
        float v = 0.f;
        if (hh >= 0 && hh < HHH)
            v = g_xx[(b*LL + hh*64 + w)*EE + e0 + ec];
        xs_s[row][w][ec] = v;
    }
    for (int idx = t; idx < 48*9; idx += 256){
        int ec = idx / 9, q = idx - ec*9;
        cw_s[ec][q] = cw[(e0+ec)*9 + q];
    }
    __syncthreads();

    for (int o = t; o < 64*48; o += 256){
        int w  = o / 48;
        int ec = o - w*48;
        float acc = cb[e0+ec];
        #pragma unroll
        for (int dh = 0; dh < 3; dh++){
            #pragma unroll
            for (int dw = 0; dw < 3; dw++){
                int ww = w + dw - 1;
                if (ww >= 0 && ww < 64)
                    acc = fmaf(xs_s[dh][ww][ec], cw_s[ec][dh*3+dw], acc);
            }
        }
        g_xc[(b*LL + h*64 + w)*EE + e0 + ec] = siluf(acc);
    }
}

// ------------------------- prep: fused k / k+2 (shared xc gather) -----------
// direction k at position l and direction k+2 at position LL-1-l read the SAME
// canonical row, so one block computes both. grid = B*2*128.
__global__ void __launch_bounds__(256) k_prep(const float* __restrict__ dtw, const float* __restrict__ dtb)
{
    __shared__ float Pt [32][39];
    __shared__ float Pt2[32][39];
    __shared__ float xr[32][193];
    __shared__ float dtws[2*EE*RR];
    __shared__ float dtbs[2*EE];
    __shared__ int   clm[32];
    const int bid = blockIdx.x;
    const int lt = bid & 127;
    const int k  = (bid >> 7) & 1;
    const int b  = bid >> 8;
    const int k2 = k + 2;
    const int l0 = lt * 32;
    const int t  = threadIdx.x;

    if (t < 32){
        int l = l0 + t, cl;
        if (k == 0) cl = l;
        else        cl = (l & 63)*64 + (l >> 6);
        clm[t] = cl;
    }
    for (int idx = t; idx < EE*RR; idx += 256){
        dtws[idx]         = dtw[k *EE*RR + idx];
        dtws[EE*RR + idx] = dtw[k2*EE*RR + idx];
    }
    for (int idx = t; idx < EE; idx += 256){
        dtbs[idx]      = dtb[k *EE + idx];
        dtbs[EE + idx] = dtb[k2*EE + idx];
    }
    __syncthreads();
    for (int idx = t; idx < 32*38; idx += 256){
        int r = idx / 38, c = idx - r*38;
        long row = (long)(b*LL + clm[r])*C152;
        Pt [r][c] = g_P[row + k *38 + c];
        Pt2[r][c] = g_P[row + k2*38 + c];
    }
    for (int idx = t; idx < 32*48; idx += 256){
        int r = idx / 48, c = idx - r*48;
        float4 v = *(const float4*)&g_xc[(b*LL + clm[r])*EE + c*4];
        xr[r][c*4+0] = v.x; xr[r][c*4+1] = v.y;
        xr[r][c*4+2] = v.z; xr[r][c*4+3] = v.w;
    }
    __syncthreads();

    const int bk  = b*KK + k;
    const int bk2 = b*KK + k2;
    if (t < EE){
        const int e = t;
        float wreg[RR], wreg2[RR];
        #pragma unroll
        for (int r = 0; r < RR; r++){
            wreg [r] = dtws[e*RR + r];
            wreg2[r] = dtws[EE*RR + e*RR + r];
        }
        const float db  = dtbs[e];
        const float db2 = dtbs[EE + e];
        #pragma unroll 4
        for (int l = 0; l < 32; l++){
            float acc = db, acc2 = db2;
            #pragma unroll
            for (int r = 0; r < RR; r++){
                acc  = fmaf(Pt [l][r], wreg [r], acc);
                acc2 = fmaf(Pt2[l][r], wreg2[r], acc2);
            }
            float dl  = softplusf(acc);
            float dl2 = softplusf(acc2);
            float u   = xr[l][e];
            g_dU2[((long)bk *LL + l0 + l)*EE + e]        = make_float2(dl,  dl*u);
            g_dU2[((long)bk2*LL + (LL-1-l0-l))*EE + e]   = make_float2(dl2, dl2*u);
        }
    }
    for (int idx = t; idx < 32*16; idx += 256){
        int pos = idx >> 4, n = idx & 15;
        long o  = ((long)bk *LL + l0 + pos)*16 + n;
        long o2 = ((long)bk2*LL + (LL-1-l0-pos))*16 + n;
        g_B4[o]  = Pt [pos][6  + n];
        g_C4[o]  = Pt [pos][22 + n];
        g_B4[o2] = Pt2[pos][6  + n];
        g_C4[o2] = Pt2[pos][22 + n];
    }
}

// ------------------------- scan pass 1: lane = full chain (16 states) -------
// block = (bk, chunk): 6 warps x 32 lanes = 192 e-chains; B staged to smem.
// chunks 0..30. grid 16*31 = 496 blocks.
__global__ void __launch_bounds__(192) k_scan1(const float* __restrict__ A_logs)
{
    __shared__ float Bs[CHL*16];       // 8KB

    const int t    = threadIdx.x;
    const int lane = t & 31;
    const int w    = t >> 5;
    const int bk    = blockIdx.x / 31;
    const int chunk = blockIdx.x - bk*31;
    const int e  = w*32 + lane;
    const int k  = bk & 3;
    const int l0 = chunk*CHL;

    {
        const float4* src = (const float4*)(g_B4 + ((long)bk*LL + l0)*16);
        float4* dst = (float4*)Bs;
        for (int i = t; i < CHL*4; i += 192) dst[i] = src[i];
    }

    const float L2E = 1.4426950408889634f;
    const int abase = (k*EE + e)*NNS;
    bool okl = true;
    #pragma unroll
    for (int n = 0; n < 16; n++){
        float av = -__expf(A_logs[abase + n]);
        okl &= fabsf(av + (float)(n+1)) < 1e-4f*(float)(n+1);
    }
    const bool ok = __all_sync(0xffffffffu, okl);

    const int ch = bk*EE + e;
    const float2* __restrict__ pdu = g_dU2 + ((long)bk*LL + l0)*EE + e;

    __syncthreads();

    u64 h2[8];
    #pragma unroll
    for (int j = 0; j < 8; j++) h2[j] = 0ull;
    float sdd = 0.f;

    if (ok){
        #pragma unroll 4
        for (int l = 0; l < CHL; l++){
            float2 du = pdu[(long)l*EE];
            float tt = ex2f(-L2E*du.x);
            float t2 = tt*tt, t4v = t2*t2;
            u64 s2 = pack2(t2,t2), s4 = pack2(t4v,t4v);
            u64 d0 = pack2(tt, t2);
            u64 d1 = mul2(d0, s2);
            u64 d2 = mul2(d0, s4);
            u64 d3 = mul2(d1, s4);
            u64 d4 = mul2(d2, s4);
            u64 d5 = mul2(d3, s4);
            u64 d6 = mul2(d4, s4);
            u64 d7 = mul2(d5, s4);
            u64 us2 = pack2(du.y, du.y);
            const u64* bp = (const u64*)(Bs + l*16);
            h2[0] = fma2(d0, h2[0], mul2(us2, bp[0]));
            h2[1] = fma2(d1, h2[1], mul2(us2, bp[1]));
            h2[2] = fma2(d2, h2[2], mul2(us2, bp[2]));
            h2[3] = fma2(d3, h2[3], mul2(us2, bp[3]));
            h2[4] = fma2(d4, h2[4], mul2(us2, bp[4]));
            h2[5] = fma2(d5, h2[5], mul2(us2, bp[5]));
            h2[6] = fma2(d6, h2[6], mul2(us2, bp[6]));
            h2[7] = fma2(d7, h2[7], mul2(us2, bp[7]));
            sdd += du.x;
        }
    } else {
        #pragma unroll 1
        for (int l = 0; l < CHL; l++){
            float2 du = pdu[(long)l*EE];
            u64 us2 = pack2(du.y, du.y);
            const u64* bp = (const u64*)(Bs + l*16);
            #pragma unroll
            for (int j = 0; j < 8; j++){
                float alo = -L2E*__expf(A_logs[abase + 2*j]);
                float ahi = -L2E*__expf(A_logs[abase + 2*j+1]);
                u64 dA = pack2(ex2f(du.x*alo), ex2f(du.x*ahi));
                h2[j] = fma2(dA, h2[j], mul2(us2, bp[j]));
            }
            sdd += du.x;
        }
    }
    u64* hfo = (u64*)&g_hfin[((long)ch*NCH + chunk)*16];
    #pragma unroll
    for (int j = 0; j < 8; j++) hfo[j] = h2[j];
    g_Sdd[ch*NCH + chunk] = sdd;
}

// ------------------------- scan mid: carry propagation ----------------------
__global__ void __launch_bounds__(256) k_scanmid(const float* __restrict__ A_logs)
{
    const int tid = blockIdx.x*256 + threadIdx.x;   // [0, 49152)
    const int ch = tid >> 4;
    const int n  = tid & 15;
    const int e  = ch % EE;
    const int k  = (ch / EE) & 3;
    float a = -__expf(A_logs[(k*EE + e)*NNS + n]);

    float h = 0.f;
    #pragma unroll
    for (int c = 0; c < NCH; c++){
        g_hin[((long)ch*NCH + c)*16 + n] = h;
        if (c < NCH-1){
            float hf = g_hfin[((long)ch*NCH + c)*16 + n];
            float S = g_Sdd[ch*NCH + c];
            h = hf + __expf(a*S)*h;
        }
    }
}

// ------------------------- scan pass 2: lane = full chain, with y -----------
// block = (bk, chunk): 192 threads; B,C staged. all 32 chunks: grid 512.
__global__ void __launch_bounds__(192) k_scan2(const float* __restrict__ A_logs)
{
    __shared__ float Bs[CHL*16];       // 8KB
    __shared__ float Cs[CHL*16];       // 8KB

    const int t    = threadIdx.x;
    const int lane = t & 31;
    const int w    = t >> 5;
    const int bk    = blockIdx.x >> 5;
    const int chunk = blockIdx.x & 31;
    const int e  = w*32 + lane;
    const int k  = bk & 3;
    const int l0 = chunk*CHL;

    {
        const float4* srcB = (const float4*)(g_B4 + ((long)bk*LL + l0)*16);
        const float4* srcC = (const float4*)(g_C4 + ((long)bk*LL + l0)*16);
        float4* dstB = (float4*)Bs;
        float4* dstC = (float4*)Cs;
        for (int i = t; i < CHL*4; i += 192){
            dstB[i] = srcB[i];
            dstC[i] = srcC[i];
        }
    }

    const float L2E = 1.4426950408889634f;
    const int abase = (k*EE + e)*NNS;
    bool okl = true;
    #pragma unroll
    for (int n = 0; n < 16; n++){
        float av = -__expf(A_logs[abase + n]);
        okl &= fabsf(av + (float)(n+1)) < 1e-4f*(float)(n+1);
    }
    const bool ok = __all_sync(0xffffffffu, okl);

    const int ch = bk*EE + e;
    const float2* __restrict__ pdu = g_dU2 + ((long)bk*LL + l0)*EE + e;
    float* __restrict__ py = g_y + ((long)bk*LL + l0)*EE + e;

    u64 h2[8];
    {
        const u64* hp = (const u64*)&g_hin[((long)ch*NCH + chunk)*16];
        #pragma unroll
        for (int j = 0; j < 8; j++) h2[j] = hp[j];
    }

    __syncthreads();

    if (ok){
        #pragma unroll 4
        for (int l = 0; l < CHL; l++){
            float2 du = pdu[(long)l*EE];
            float tt = ex2f(-L2E*du.x);
            float t2 = tt*tt, t4v = t2*t2;
            u64 s2 = pack2(t2,t2), s4 = pack2(t4v,t4v);
            u64 d0 = pack2(tt, t2);
            u64 d1 = mul2(d0, s2);
            u64 d2 = mul2(d0, s4);
            u64 d3 = mul2(d1, s4);
            u64 d4 = mul2(d2, s4);
            u64 d5 = mul2(d3, s4);
            u64 d6 = mul2(d4, s4);
            u64 d7 = mul2(d5, s4);
            u64 us2 = pack2(du.y, du.y);
            const u64* bp = (const u64*)(Bs + l*16);
            const u64* cp = (const u64*)(Cs + l*16);
            h2[0] = fma2(d0, h2[0], mul2(us2, bp[0]));
            h2[1] = fma2(d1, h2[1], mul2(us2, bp[1]));
            h2[2] = fma2(d2, h2[2], mul2(us2, bp[2]));
            h2[3] = fma2(d3, h2[3], mul2(us2, bp[3]));
            h2[4] = fma2(d4, h2[4], mul2(us2, bp[4]));
            h2[5] = fma2(d5, h2[5], mul2(us2, bp[5]));
            h2[6] = fma2(d6, h2[6], mul2(us2, bp[6]));
            h2[7] = fma2(d7, h2[7], mul2(us2, bp[7]));
            u64 acc = mul2(h2[0], cp[0]);
            acc = fma2(h2[1], cp[1], acc);
            acc = fma2(h2[2], cp[2], acc);
            acc = fma2(h2[3], cp[3], acc);
            acc = fma2(h2[4], cp[4], acc);
            acc = fma2(h2[5], cp[5], acc);
            acc = fma2(h2[6], cp[6], acc);
            acc = fma2(h2[7], cp[7], acc);
            float lo, hi; unpack2(acc, lo, hi);
            py[(long)l*EE] = lo + hi;
        }
    } else {
        #pragma unroll 1
        for (int l = 0; l < CHL; l++){
            float2 du = pdu[(long)l*EE];
            u64 us2 = pack2(du.y, du.y);
            const u64* bp = (const u64*)(Bs + l*16);
            const u64* cp = (const u64*)(Cs + l*16);
            u64 acc = 0ull;
            #pragma unroll
            for (int j = 0; j < 8; j++){
                float alo = -L2E*__expf(A_logs[abase + 2*j]);
                float ahi = -L2E*__expf(A_logs[abase + 2*j+1]);
                u64 dA = pack2(ex2f(du.x*alo), ex2f(du.x*ahi));
                h2[j] = fma2(dA, h2[j], mul2(us2, bp[j]));
                acc = fma2(h2[j], cp[j], acc);
            }
            float lo, hi; unpack2(acc, lo, hi);
            py[(long)l*EE] = lo + hi;
        }
    }
}

// ------------------------- merge + D*xc + LayerNorm + gate ------------------
__global__ void __launch_bounds__(256) k_merge(const float* __restrict__ Ds, const float* __restrict__ gamma,
                        const float* __restrict__ beta)
{
    __shared__ float sumD[EE];
    const int l0 = blockIdx.x * 32;
    const int b  = blockIdx.y;
    const int t  = threadIdx.x;
    if (t < EE) sumD[t] = Ds[t] + Ds[EE + t] + Ds[2*EE + t] + Ds[3*EE + t];
    __syncthreads();

    const int li = t >> 3, ts = t & 7;
    const int l  = l0 + li;
    const int lw = (l & 63)*64 + (l >> 6);

    const float* __restrict__ y0p = g_y + ((long)(b*4 + 0)*LL + l)*EE;
    const float* __restrict__ y1p = g_y + ((long)(b*4 + 1)*LL + lw)*EE;
    const float* __restrict__ y2p = g_y + ((long)(b*4 + 2)*LL + (LL-1-l))*EE;
    const float* __restrict__ y3p = g_y + ((long)(b*4 + 3)*LL + (LL-1-lw))*EE;
    const float* __restrict__ xcp = g_xc + (long)(b*LL + l)*EE;
    const float* __restrict__ zp  = g_z  + (long)(b*LL + l)*EE;
    float* __restrict__ ymp = g_ym + (long)(b*LL + l)*EE;

    float v[6][4];
    float s1 = 0.f, s2 = 0.f;
    #pragma unroll
    for (int m = 0; m < 6; m++){
        int e4 = (ts + 8*m)*4;
        float4 a0 = *(const float4*)(y0p + e4);
        float4 a1 = *(const float4*)(y1p + e4);
        float4 a2 = *(const float4*)(y2p + e4);
        float4 a3 = *(const float4*)(y3p + e4);
        float4 xc = *(const float4*)(xcp + e4);
        float4 sd = *(const float4*)(&sumD[e4]);
        v[m][0] = a0.x + a1.x + a2.x + a3.x + sd.x*xc.x;
        v[m][1] = a0.y + a1.y + a2.y + a3.y + sd.y*xc.y;
        v[m][2] = a0.z + a1.z + a2.z + a3.z + sd.z*xc.z;
        v[m][3] = a0.w + a1.w + a2.w + a3.w + sd.w*xc.w;
        #pragma unroll
        for (int q = 0; q < 4; q++){ s1 += v[m][q]; s2 += v[m][q]*v[m][q]; }
    }
    #pragma unroll
    for (int o = 1; o < 8; o <<= 1){
        s1 += __shfl_xor_sync(0xffffffffu, s1, o);
        s2 += __shfl_xor_sync(0xffffffffu, s2, o);
    }
    const float inv = 1.f / (float)EE;
    float mu = s1 * inv;
    float var = s2 * inv - mu*mu;
    float rstd = rsqrtf(var + 1e-5f);

    #pragma unroll
    for (int m = 0; m < 6; m++){
        int e4 = (ts + 8*m)*4;
        float4 gm = *(const float4*)(gamma + e4);
        float4 bt = *(const float4*)(beta + e4);
        float4 zz = *(const float4*)(zp + e4);
        float4 o4;
        o4.x = ((v[m][0]-mu)*rstd*gm.x + bt.x) * zz.x;
        o4.y = ((v[m][1]-mu)*rstd*gm.y + bt.y) * zz.y;
        o4.z = ((v[m][2]-mu)*rstd*gm.z + bt.z) * zz.z;
        o4.w = ((v[m][3]-mu)*rstd*gm.w + bt.w) * zz.w;
        *(float4*)(ymp + e4) = o4;
    }
}

// ------------------------- launcher -----------------------------------------
extern "C" void kernel_launch(void* const* d_in, const int* in_sizes, int n_in,
                              void* d_out, int out_size)
{
    const float* x    = (const float*)d_in[0];
    const float* ipw  = (const float*)d_in[1];
    const float* cw   = (const float*)d_in[2];
    const float* cb   = (const float*)d_in[3];
    const float* xpw  = (const float*)d_in[4];
    const float* dtw  = (const float*)d_in[5];
    const float* dtb  = (const float*)d_in[6];
    const float* alog = (const float*)d_in[7];
    const float* Ds   = (const float*)d_in[8];
    const float* lng  = (const float*)d_in[9];
    const float* lnb  = (const float*)d_in[10];
    const float* opw  = (const float*)d_in[11];
    float* out = (float*)d_out;

    k_gemm<DM, 1><<<dim3(128, 6), 256>>>(x, ipw, nullptr, 2*EE);
    k_conv<<<dim3(4, 64, BB), 256>>>(cw, cb);
    k_gemm<EE, 0><<<dim3(128, 3), 256>>>(nullptr, xpw, nullptr, C152);
    k_prep<<<BB*2*128, 256>>>(dtw, dtb);
    k_scan1<<<16*31, 192>>>(alog);
    k_scanmid<<<192, 256>>>(alog);
    k_scan2<<<16*32, 192>>>(alog);
    k_merge<<<dim3(128, BB), 256>>>(Ds, lng, lnb);
    k_gemm<EE, 2><<<dim3(128, 2), 256>>>(nullptr, opw, out, DM);
}

// round 17
// speedup vs baseline: 1.0877x; 1.0363x over previous
#include <cuda_runtime.h>
#include <cuda_fp16.h>

#define BB 4
#define HHH 64
#define LL 4096
#define EE 192
#define NNS 16
#define RR 6
#define KK 4
#define DM 96
#define BL (BB*LL)
#define C152 152
#define NCH 32
#define CHL 128   // LL/NCH

typedef unsigned long long u64;

// ------------------------- device scratch (no allocations) ------------------
__device__ float g_xx[BL*EE];
__device__ float g_z [BL*EE];
__device__ float g_xc[BL*EE];
__device__ float g_P [BL*C152];
__device__ __half2 g_dUh[16*LL*EE];    // {delta, delta*u} fp16 in (bk, l, e)
__device__ float g_B4[16*LL*16];       // (bk, l, n) natural state order
__device__ float g_C4[16*LL*16];
__device__ float g_y [16*LL*EE];       // (bk, l, e)
__device__ float g_ym[BL*EE];
// chunked-scan carries: chain = bk*EE+e in [0,3072); natural state order n
__device__ float g_hfin[3072*NCH*16];
__device__ float g_hin [3072*NCH*16];
__device__ float g_Sdd [3072*NCH];

__device__ __forceinline__ float ex2f(float x){
    float y; asm("ex2.approx.f32 %0, %1;" : "=f"(y) : "f"(x)); return y;
}
__device__ __forceinline__ float siluf(float x){
    return x / (1.f + __expf(-x));
}
__device__ __forceinline__ float softplusf(float x){
    return fmaxf(x, 0.f) + __logf(1.f + __expf(-fabsf(x)));
}
__device__ __forceinline__ u64 fma2(u64 a, u64 b, u64 c){
    u64 d; asm("fma.rn.f32x2 %0, %1, %2, %3;" : "=l"(d) : "l"(a), "l"(b), "l"(c));
    return d;
}
__device__ __forceinline__ u64 mul2(u64 a, u64 b){
    u64 d; asm("mul.rn.f32x2 %0, %1, %2;" : "=l"(d) : "l"(a), "l"(b));
    return d;
}
__device__ __forceinline__ u64 pack2(float x, float y){
    u64 d; asm("mov.b64 %0, {%1, %2};" : "=l"(d) : "f"(x), "f"(y));
    return d;
}
__device__ __forceinline__ void unpack2(u64 v, float& lo, float& hi){
    asm("mov.b64 {%0, %1}, %2;" : "=f"(lo), "=f"(hi) : "l"(v));
}

// ------------------------- tiled GEMM: out[m,n] = sum_k X[m,k]*W[n,k] -------
template<int KD, int MODE>
__global__ void __launch_bounds__(256)
k_gemm(const float* __restrict__ Xp, const float* __restrict__ W,
       float* __restrict__ Out, int Nn)
{
    __shared__ float Xs[32][132];
    __shared__ float Ws[32][68];
    const float* __restrict__ X = (MODE==0) ? (const float*)g_xc
                                : (MODE==2) ? (const float*)g_ym : Xp;
    const int m0 = blockIdx.x * 128;
    const int n0 = blockIdx.y * 64;
    const int t  = threadIdx.x;
    const int ty = t >> 4, tx = t & 15;
    u64 acc2[4][4];
    #pragma unroll
    for (int i=0;i<4;i++)
        #pragma unroll
        for (int j=0;j<4;j++) acc2[i][j] = 0ull;

    const int lc4 = (t & 7) * 4;
    const int lr0 = t >> 3;
    const int NKC = KD/32;

    float4 xv[4], wv2[2];
    #pragma unroll
    for (int i = 0; i < 4; i++)
        xv[i] = *(const float4*)&X[(m0 + lr0 + 32*i)*KD + lc4];
    #pragma unroll
    for (int i = 0; i < 2; i++){
        int nr = n0 + lr0 + 32*i;
        wv2[i] = (nr < Nn) ? *(const float4*)&W[nr*KD + lc4]
                           : make_float4(0.f,0.f,0.f,0.f);
    }

    #pragma unroll
    for (int kc = 0; kc < NKC; kc++){
        #pragma unroll
        for (int i = 0; i < 4; i++){
            int r = lr0 + 32*i;
            Xs[lc4+0][r] = xv[i].x; Xs[lc4+1][r] = xv[i].y;
            Xs[lc4+2][r] = xv[i].z; Xs[lc4+3][r] = xv[i].w;
        }
        #pragma unroll
        for (int i = 0; i < 2; i++){
            int r = lr0 + 32*i;
            Ws[lc4+0][r] = wv2[i].x; Ws[lc4+1][r] = wv2[i].y;
            Ws[lc4+2][r] = wv2[i].z; Ws[lc4+3][r] = wv2[i].w;
        }
        __syncthreads();

        if (kc + 1 < NKC){
            #pragma unroll
            for (int i = 0; i < 4; i++)
                xv[i] = *(const float4*)&X[(m0 + lr0 + 32*i)*KD + (kc+1)*32 + lc4];
            #pragma unroll
            for (int i = 0; i < 2; i++){
                int nr = n0 + lr0 + 32*i;
                wv2[i] = (nr < Nn) ? *(const float4*)&W[nr*KD + (kc+1)*32 + lc4]
                                   : make_float4(0.f,0.f,0.f,0.f);
            }
        }

        #pragma unroll
        for (int k = 0; k < 32; k++){
            const u64* xp = (const u64*)&Xs[k][ty*8];
            u64 x2[4] = {xp[0], xp[1], xp[2], xp[3]};
            float4 wv = *(const float4*)&Ws[k][tx*4];
            u64 w2[4] = {pack2(wv.x,wv.x), pack2(wv.y,wv.y),
                         pack2(wv.z,wv.z), pack2(wv.w,wv.w)};
            #pragma unroll
            for (int i=0;i<4;i++)
                #pragma unroll
                for (int j=0;j<4;j++) acc2[i][j] = fma2(x2[i], w2[j], acc2[i][j]);
        }
        __syncthreads();
    }
    #pragma unroll
    for (int i=0;i<4;i++){
        #pragma unroll
        for (int j=0;j<4;j++){
            float lo, hi;
            unpack2(acc2[i][j], lo, hi);
            int n = n0 + tx*4 + j;
            int mA = m0 + ty*8 + 2*i;
            #pragma unroll
            for (int pp = 0; pp < 2; pp++){
                int m = mA + pp;
                float v = pp ? hi : lo;
                if (MODE == 1){
                    if (n < EE) g_xx[m*EE + n] = v;
                    else        g_z [m*EE + n - EE] = siluf(v);
                } else if (MODE == 0){
                    if (n < Nn) g_P[m*C152 + n] = v;
                } else {
                    if (n < Nn) Out[m*Nn + n] = v;
                }
            }
        }
    }
}

// ------------------------- depthwise 3x3 conv + bias + silu -----------------
__global__ void __launch_bounds__(256) k_conv(const float* __restrict__ cw, const float* __restrict__ cb)
{
    __shared__ float xs_s[3][64][48];
    __shared__ float cw_s[48][9];
    const int e0 = blockIdx.x * 48;
    const int h  = blockIdx.y;
    const int b  = blockIdx.z;
    const int t  = threadIdx.x;

    for (int idx = t; idx < 3*64*48; idx += 256){
        int row = idx / (64*48);
        int rem = idx - row*(64*48);
        int w  = rem / 48;
        int ec = rem - w*48;
        int hh = h + row - 1;
        float v = 0.f;
        if (hh >= 0 && hh < HHH)
            v = g_xx[(b*LL + hh*64 + w)*EE + e0 + ec];
        xs_s[row][w][ec] = v;
    }
    for (int idx = t; idx < 48*9; idx += 256){
        int ec = idx / 9, q = idx - ec*9;
        cw_s[ec][q] = cw[(e0+ec)*9 + q];
    }
    __syncthreads();

    for (int o = t; o < 64*48; o += 256){
        int w  = o / 48;
        int ec = o - w*48;
        float acc = cb[e0+ec];
        #pragma unroll
        for (int dh = 0; dh < 3; dh++){
            #pragma unroll
            for (int dw = 0; dw < 3; dw++){
                int ww = w + dw - 1;
                if (ww >= 0 && ww < 64)
                    acc = fmaf(xs_s[dh][ww][ec], cw_s[ec][dh*3+dw], acc);
            }
        }
        g_xc[(b*LL + h*64 + w)*EE + e0 + ec] = siluf(acc);
    }
}

// ------------------------- prep: fused k / k+2 (shared xc gather) -----------
__global__ void __launch_bounds__(256) k_prep(const float* __restrict__ dtw, const float* __restrict__ dtb)
{
    __shared__ float Pt [32][39];
    __shared__ float Pt2[32][39];
    __shared__ float xr[32][193];
    __shared__ float dtws[2*EE*RR];
    __shared__ float dtbs[2*EE];
    __shared__ int   clm[32];
    const int bid = blockIdx.x;
    const int lt = bid & 127;
    const int k  = (bid >> 7) & 1;
    const int b  = bid >> 8;
    const int k2 = k + 2;
    const int l0 = lt * 32;
    const int t  = threadIdx.x;

    if (t < 32){
        int l = l0 + t, cl;
        if (k == 0) cl = l;
        else        cl = (l & 63)*64 + (l >> 6);
        clm[t] = cl;
    }
    for (int idx = t; idx < EE*RR; idx += 256){
        dtws[idx]         = dtw[k *EE*RR + idx];
        dtws[EE*RR + idx] = dtw[k2*EE*RR + idx];
    }
    for (int idx = t; idx < EE; idx += 256){
        dtbs[idx]      = dtb[k *EE + idx];
        dtbs[EE + idx] = dtb[k2*EE + idx];
    }
    __syncthreads();
    for (int idx = t; idx < 32*38; idx += 256){
        int r = idx / 38, c = idx - r*38;
        long row = (long)(b*LL + clm[r])*C152;
        Pt [r][c] = g_P[row + k *38 + c];
        Pt2[r][c] = g_P[row + k2*38 + c];
    }
    for (int idx = t; idx < 32*48; idx += 256){
        int r = idx / 48, c = idx - r*48;
        float4 v = *(const float4*)&g_xc[(b*LL + clm[r])*EE + c*4];
        xr[r][c*4+0] = v.x; xr[r][c*4+1] = v.y;
        xr[r][c*4+2] = v.z; xr[r][c*4+3] = v.w;
    }
    __syncthreads();

    const int bk  = b*KK + k;
    const int bk2 = b*KK + k2;
    if (t < EE){
        const int e = t;
        float wreg[RR], wreg2[RR];
        #pragma unroll
        for (int r = 0; r < RR; r++){
            wreg [r] = dtws[e*RR + r];
            wreg2[r] = dtws[EE*RR + e*RR + r];
        }
        const float db  = dtbs[e];
        const float db2 = dtbs[EE + e];
        #pragma unroll 4
        for (int l = 0; l < 32; l++){
            float acc = db, acc2 = db2;
            #pragma unroll
            for (int r = 0; r < RR; r++){
                acc  = fmaf(Pt [l][r], wreg [r], acc);
                acc2 = fmaf(Pt2[l][r], wreg2[r], acc2);
            }
            float dl  = softplusf(acc);
            float dl2 = softplusf(acc2);
            float u   = xr[l][e];
            g_dUh[((long)bk *LL + l0 + l)*EE + e]      = __floats2half2_rn(dl,  dl*u);
            g_dUh[((long)bk2*LL + (LL-1-l0-l))*EE + e] = __floats2half2_rn(dl2, dl2*u);
        }
    }
    for (int idx = t; idx < 32*16; idx += 256){
        int pos = idx >> 4, n = idx & 15;
        long o  = ((long)bk *LL + l0 + pos)*16 + n;
        long o2 = ((long)bk2*LL + (LL-1-l0-pos))*16 + n;
        g_B4[o]  = Pt [pos][6  + n];
        g_C4[o]  = Pt [pos][22 + n];
        g_B4[o2] = Pt2[pos][6  + n];
        g_C4[o2] = Pt2[pos][22 + n];
    }
}

// ------------------------- scan pass 1: lane = full chain (16 states) -------
// block = (bk, chunk): 6 warps x 32 lanes = 192 e-chains; B staged to smem.
// chunks 0..30. grid 16*31 = 496 blocks.
__global__ void __launch_bounds__(192) k_scan1(const float* __restrict__ A_logs)
{
    __shared__ float Bs[CHL*16];       // 8KB

    const int t    = threadIdx.x;
    const int lane = t & 31;
    const int w    = t >> 5;
    const int bk    = blockIdx.x / 31;
    const int chunk = blockIdx.x - bk*31;
    const int e  = w*32 + lane;
    const int k  = bk & 3;
    const int l0 = chunk*CHL;

    {
        const float4* src = (const float4*)(g_B4 + ((long)bk*LL + l0)*16);
        float4* dst = (float4*)Bs;
        for (int i = t; i < CHL*4; i += 192) dst[i] = src[i];
    }

    const float L2E = 1.4426950408889634f;
    const int abase = (k*EE + e)*NNS;
    bool okl = true;
    #pragma unroll
    for (int n = 0; n < 16; n++){
        float av = -__expf(A_logs[abase + n]);
        okl &= fabsf(av + (float)(n+1)) < 1e-4f*(float)(n+1);
    }
    const bool ok = __all_sync(0xffffffffu, okl);

    const int ch = bk*EE + e;
    const __half2* __restrict__ pdu = g_dUh + ((long)bk*LL + l0)*EE + e;

    __syncthreads();

    u64 h2[8];
    #pragma unroll
    for (int j = 0; j < 8; j++) h2[j] = 0ull;
    float sdd = 0.f;

    if (ok){
        #pragma unroll 4
        for (int l = 0; l < CHL; l++){
            float2 du = __half22float2(pdu[(long)l*EE]);
            float tt = ex2f(-L2E*du.x);
            float t2 = tt*tt, t4v = t2*t2;
            u64 s2 = pack2(t2,t2), s4 = pack2(t4v,t4v);
            u64 d0 = pack2(tt, t2);
            u64 d1 = mul2(d0, s2);
            u64 d2 = mul2(d0, s4);
            u64 d3 = mul2(d1, s4);
            u64 d4 = mul2(d2, s4);
            u64 d5 = mul2(d3, s4);
            u64 d6 = mul2(d4, s4);
            u64 d7 = mul2(d5, s4);
            u64 us2 = pack2(du.y, du.y);
            const u64* bp = (const u64*)(Bs + l*16);
            h2[0] = fma2(d0, h2[0], mul2(us2, bp[0]));
            h2[1] = fma2(d1, h2[1], mul2(us2, bp[1]));
            h2[2] = fma2(d2, h2[2], mul2(us2, bp[2]));
            h2[3] = fma2(d3, h2[3], mul2(us2, bp[3]));
            h2[4] = fma2(d4, h2[4], mul2(us2, bp[4]));
            h2[5] = fma2(d5, h2[5], mul2(us2, bp[5]));
            h2[6] = fma2(d6, h2[6], mul2(us2, bp[6]));
            h2[7] = fma2(d7, h2[7], mul2(us2, bp[7]));
            sdd += du.x;
        }
    } else {
        #pragma unroll 1
        for (int l = 0; l < CHL; l++){
            float2 du = __half22float2(pdu[(long)l*EE]);
            u64 us2 = pack2(du.y, du.y);
            const u64* bp = (const u64*)(Bs + l*16);
            #pragma unroll
            for (int j = 0; j < 8; j++){
                float alo = -L2E*__expf(A_logs[abase + 2*j]);
                float ahi = -L2E*__expf(A_logs[abase + 2*j+1]);
                u64 dA = pack2(ex2f(du.x*alo), ex2f(du.x*ahi));
                h2[j] = fma2(dA, h2[j], mul2(us2, bp[j]));
            }
            sdd += du.x;
        }
    }
    u64* hfo = (u64*)&g_hfin[((long)ch*NCH + chunk)*16];
    #pragma unroll
    for (int j = 0; j < 8; j++) hfo[j] = h2[j];
    g_Sdd[ch*NCH + chunk] = sdd;
}

// ------------------------- scan mid: carry propagation ----------------------
__global__ void __launch_bounds__(256) k_scanmid(const float* __restrict__ A_logs)
{
    const int tid = blockIdx.x*256 + threadIdx.x;   // [0, 49152)
    const int ch = tid >> 4;
    const int n  = tid & 15;
    const int e  = ch % EE;
    const int k  = (ch / EE) & 3;
    float a = -__expf(A_logs[(k*EE + e)*NNS + n]);

    float h = 0.f;
    #pragma unroll
    for (int c = 0; c < NCH; c++){
        g_hin[((long)ch*NCH + c)*16 + n] = h;
        if (c < NCH-1){
            float hf = g_hfin[((long)ch*NCH + c)*16 + n];
            float S = g_Sdd[ch*NCH + c];
            h = hf + __expf(a*S)*h;
        }
    }
}

// ------------------------- scan pass 2: lane = full chain, with y -----------
// block = (bk, chunk): 192 threads; B,C staged. all 32 chunks: grid 512.
// block order REVERSED vs scan1 so scan2 starts on scan1's L2-hot tail.
__global__ void __launch_bounds__(192) k_scan2(const float* __restrict__ A_logs)
{
    __shared__ float Bs[CHL*16];       // 8KB
    __shared__ float Cs[CHL*16];       // 8KB

    const int t    = threadIdx.x;
    const int lane = t & 31;
    const int w    = t >> 5;
    const int bid  = gridDim.x - 1 - blockIdx.x;   // reversed launch order
    const int bk    = bid >> 5;
    const int chunk = bid & 31;
    const int e  = w*32 + lane;
    const int k  = bk & 3;
    const int l0 = chunk*CHL;

    {
        const float4* srcB = (const float4*)(g_B4 + ((long)bk*LL + l0)*16);
        const float4* srcC = (const float4*)(g_C4 + ((long)bk*LL + l0)*16);
        float4* dstB = (float4*)Bs;
        float4* dstC = (float4*)Cs;
        for (int i = t; i < CHL*4; i += 192){
            dstB[i] = srcB[i];
            dstC[i] = srcC[i];
        }
    }

    const float L2E = 1.4426950408889634f;
    const int abase = (k*EE + e)*NNS;
    bool okl = true;
    #pragma unroll
    for (int n = 0; n < 16; n++){
        float av = -__expf(A_logs[abase + n]);
        okl &= fabsf(av + (float)(n+1)) < 1e-4f*(float)(n+1);
    }
    const bool ok = __all_sync(0xffffffffu, okl);

    const int ch = bk*EE + e;
    const __half2* __restrict__ pdu = g_dUh + ((long)bk*LL + l0)*EE + e;
    float* __restrict__ py = g_y + ((long)bk*LL + l0)*EE + e;

    u64 h2[8];
    {
        const u64* hp = (const u64*)&g_hin[((long)ch*NCH + chunk)*16];
        #pragma unroll
        for (int j = 0; j < 8; j++) h2[j] = hp[j];
    }

    __syncthreads();

    if (ok){
        #pragma unroll 4
        for (int l = 0; l < CHL; l++){
            float2 du = __half22float2(pdu[(long)l*EE]);
            float tt = ex2f(-L2E*du.x);
            float t2 = tt*tt, t4v = t2*t2;
            u64 s2 = pack2(t2,t2), s4 = pack2(t4v,t4v);
            u64 d0 = pack2(tt, t2);
            u64 d1 = mul2(d0, s2);
            u64 d2 = mul2(d0, s4);
            u64 d3 = mul2(d1, s4);
            u64 d4 = mul2(d2, s4);
            u64 d5 = mul2(d3, s4);
            u64 d6 = mul2(d4, s4);
            u64 d7 = mul2(d5, s4);
            u64 us2 = pack2(du.y, du.y);
            const u64* bp = (const u64*)(Bs + l*16);
            const u64* cp = (const u64*)(Cs + l*16);
            h2[0] = fma2(d0, h2[0], mul2(us2, bp[0]));
            h2[1] = fma2(d1, h2[1], mul2(us2, bp[1]));
            h2[2] = fma2(d2, h2[2], mul2(us2, bp[2]));
            h2[3] = fma2(d3, h2[3], mul2(us2, bp[3]));
            h2[4] = fma2(d4, h2[4], mul2(us2, bp[4]));
            h2[5] = fma2(d5, h2[5], mul2(us2, bp[5]));
            h2[6] = fma2(d6, h2[6], mul2(us2, bp[6]));
            h2[7] = fma2(d7, h2[7], mul2(us2, bp[7]));
            u64 acc = mul2(h2[0], cp[0]);
            acc = fma2(h2[1], cp[1], acc);
            acc = fma2(h2[2], cp[2], acc);
            acc = fma2(h2[3], cp[3], acc);
            acc = fma2(h2[4], cp[4], acc);
            acc = fma2(h2[5], cp[5], acc);
            acc = fma2(h2[6], cp[6], acc);
            acc = fma2(h2[7], cp[7], acc);
            float lo, hi; unpack2(acc, lo, hi);
            py[(long)l*EE] = lo + hi;
        }
    } else {
        #pragma unroll 1
        for (int l = 0; l < CHL; l++){
            float2 du = __half22float2(pdu[(long)l*EE]);
            u64 us2 = pack2(du.y, du.y);
            const u64* bp = (const u64*)(Bs + l*16);
            const u64* cp = (const u64*)(Cs + l*16);
            u64 acc = 0ull;
            #pragma unroll
            for (int j = 0; j < 8; j++){
                float alo = -L2E*__expf(A_logs[abase + 2*j]);
                float ahi = -L2E*__expf(A_logs[abase + 2*j+1]);
                u64 dA = pack2(ex2f(du.x*alo), ex2f(du.x*ahi));
                h2[j] = fma2(dA, h2[j], mul2(us2, bp[j]));
                acc = fma2(h2[j], cp[j], acc);
            }
            float lo, hi; unpack2(acc, lo, hi);
            py[(long)l*EE] = lo + hi;
        }
    }
}

// ------------------------- merge + D*xc + LayerNorm + gate ------------------
__global__ void __launch_bounds__(256) k_merge(const float* __restrict__ Ds, const float* __restrict__ gamma,
                        const float* __restrict__ beta)
{
    __shared__ float sumD[EE];
    const int l0 = blockIdx.x * 32;
    const int b  = blockIdx.y;
    const int t  = threadIdx.x;
    if (t < EE) sumD[t] = Ds[t] + Ds[EE + t] + Ds[2*EE + t] + Ds[3*EE + t];
    __syncthreads();

    const int li = t >> 3, ts = t & 7;
    const int l  = l0 + li;
    const int lw = (l & 63)*64 + (l >> 6);

    const float* __restrict__ y0p = g_y + ((long)(b*4 + 0)*LL + l)*EE;
    const float* __restrict__ y1p = g_y + ((long)(b*4 + 1)*LL + lw)*EE;
    const float* __restrict__ y2p = g_y + ((long)(b*4 + 2)*LL + (LL-1-l))*EE;
    const float* __restrict__ y3p = g_y + ((long)(b*4 + 3)*LL + (LL-1-lw))*EE;
    const float* __restrict__ xcp = g_xc + (long)(b*LL + l)*EE;
    const float* __restrict__ zp  = g_z  + (long)(b*LL + l)*EE;
    float* __restrict__ ymp = g_ym + (long)(b*LL + l)*EE;

    float v[6][4];
    float s1 = 0.f, s2 = 0.f;
    #pragma unroll
    for (int m = 0; m < 6; m++){
        int e4 = (ts + 8*m)*4;
        float4 a0 = *(const float4*)(y0p + e4);
        float4 a1 = *(const float4*)(y1p + e4);
        float4 a2 = *(const float4*)(y2p + e4);
        float4 a3 = *(const float4*)(y3p + e4);
        float4 xc = *(const float4*)(xcp + e4);
        float4 sd = *(const float4*)(&sumD[e4]);
        v[m][0] = a0.x + a1.x + a2.x + a3.x + sd.x*xc.x;
        v[m][1] = a0.y + a1.y + a2.y + a3.y + sd.y*xc.y;
        v[m][2] = a0.z + a1.z + a2.z + a3.z + sd.z*xc.z;
        v[m][3] = a0.w + a1.w + a2.w + a3.w + sd.w*xc.w;
        #pragma unroll
        for (int q = 0; q < 4; q++){ s1 += v[m][q]; s2 += v[m][q]*v[m][q]; }
    }
    #pragma unroll
    for (int o = 1; o < 8; o <<= 1){
        s1 += __shfl_xor_sync(0xffffffffu, s1, o);
        s2 += __shfl_xor_sync(0xffffffffu, s2, o);
    }
    const float inv = 1.f / (float)EE;
    float mu = s1 * inv;
    float var = s2 * inv - mu*mu;
    float rstd = rsqrtf(var + 1e-5f);

    #pragma unroll
    for (int m = 0; m < 6; m++){
        int e4 = (ts + 8*m)*4;
        float4 gm = *(const float4*)(gamma + e4);
        float4 bt = *(const float4*)(beta + e4);
        float4 zz = *(const float4*)(zp + e4);
        float4 o4;
        o4.x = ((v[m][0]-mu)*rstd*gm.x + bt.x) * zz.x;
        o4.y = ((v[m][1]-mu)*rstd*gm.y + bt.y) * zz.y;
        o4.z = ((v[m][2]-mu)*rstd*gm.z + bt.z) * zz.z;
        o4.w = ((v[m][3]-mu)*rstd*gm.w + bt.w) * zz.w;
        *(float4*)(ymp + e4) = o4;
    }
}

// ------------------------- launcher -----------------------------------------
extern "C" void kernel_launch(void* const* d_in, const int* in_sizes, int n_in,
                              void* d_out, int out_size)
{
    const float* x    = (const float*)d_in[0];
    const float* ipw  = (const float*)d_in[1];
    const float* cw   = (const float*)d_in[2];
    const float* cb   = (const float*)d_in[3];
    const float* xpw  = (const float*)d_in[4];
    const float* dtw  = (const float*)d_in[5];
    const float* dtb  = (const float*)d_in[6];
    const float* alog = (const float*)d_in[7];
    const float* Ds   = (const float*)d_in[8];
    const float* lng  = (const float*)d_in[9];
    const float* lnb  = (const float*)d_in[10];
    const float* opw  = (const float*)d_in[11];
    float* out = (float*)d_out;

    k_gemm<DM, 1><<<dim3(128, 6), 256>>>(x, ipw, nullptr, 2*EE);
    k_conv<<<dim3(4, 64, BB), 256>>>(cw, cb);
    k_gemm<EE, 0><<<dim3(128, 3), 256>>>(nullptr, xpw, nullptr, C152);
    k_prep<<<BB*2*128, 256>>>(dtw, dtb);
    k_scan1<<<16*31, 192>>>(alog);
    k_scanmid<<<192, 256>>>(alog);
    k_scan2<<<16*32, 192>>>(alog);
    k_merge<<<dim3(128, BB), 256>>>(Ds, lng, lnb);
    k_gemm<EE, 2><<<dim3(128, 2), 256>>>(nullptr, opw, out, DM);
}